// round 9
// baseline (speedup 1.0000x reference)
#include <cuda_runtime.h>
#include <cstdint>
#include <cmath>

#define NB     4
#define LQ     4096
#define LKV    512
#define DATTN  1024
#define NHEADS 16
#define HDIM   64

// Scratch (device globals: allocation-free rule)
__device__ float g_qh[NB * LQ * DATTN];        // 64 MB
__device__ float g_kv[NB * LKV * 2 * DATTN];   // 16 MB
__device__ float g_attn[NB * LQ * DATTN];      // 64 MB
// tf32-pre-rounded operands
__device__ float g_qr[NB * LQ * 1024];
__device__ float g_kvsr[NB * LKV * 1024];
__device__ float g_wq[DATTN * 1024];
__device__ float g_wkv[2 * DATTN * 1024];
__device__ float g_wo[1024 * DATTN];

__device__ __forceinline__ uint32_t f2tf32(float x) {
    uint32_t y;
    asm("cvt.rna.tf32.f32 %0, %1;" : "=r"(y) : "f"(x));
    return y;
}

__device__ __forceinline__ void mma8(float* d, const uint32_t* a, const uint32_t* b) {
    asm volatile(
        "mma.sync.aligned.m16n8k8.row.col.f32.tf32.tf32.f32 "
        "{%0,%1,%2,%3}, {%4,%5,%6,%7}, {%8,%9}, {%0,%1,%2,%3};\n"
        : "+f"(d[0]), "+f"(d[1]), "+f"(d[2]), "+f"(d[3])
        : "r"(a[0]), "r"(a[1]), "r"(a[2]), "r"(a[3]), "r"(b[0]), "r"(b[1]));
}

__device__ __forceinline__ void ldsm_x4(uint32_t& r0, uint32_t& r1, uint32_t& r2,
                                        uint32_t& r3, const float* p) {
    uint32_t addr = (uint32_t)__cvta_generic_to_shared(p);
    asm volatile("ldmatrix.sync.aligned.m8n8.x4.shared.b16 {%0,%1,%2,%3}, [%4];"
                 : "=r"(r0), "=r"(r1), "=r"(r2), "=r"(r3) : "r"(addr));
}

// Elementwise round-to-tf32 (bits kept in fp32 storage)
__global__ void __launch_bounds__(256)
round_tf32(const float4* __restrict__ src, float4* __restrict__ dst, int n4) {
    int i = blockIdx.x * blockDim.x + threadIdx.x;
    if (i < n4) {
        float4 v = src[i];
        float4 o;
        o.x = __uint_as_float(f2tf32(v.x));
        o.y = __uint_as_float(f2tf32(v.y));
        o.z = __uint_as_float(f2tf32(v.z));
        o.w = __uint_as_float(f2tf32(v.w));
        dst[i] = o;
    }
}

#define SA     36                         // smem row stride (32 + 4 pad) words
#define STAGES 3
#define AW     (128 * SA)                 // A tile words per stage
#define BW     (256 * SA)                 // B tile words per stage
#define SMEM_BYTES (STAGES * (AW + BW) * 4)   // 165888

// C[M,N] = A[M,K] * B[N,K]^T. A,B already tf32-valued fp32 bits.
// Block tile 128M x 256N, 8 warps of 64x64 (2M x 4N). 3-stage cp.async.
// Two jobs packed into one grid: blocks [0,split) = job0, rest = job1.
__global__ void __launch_bounds__(256)
gemm_tf32(const float* __restrict__ A0, const float* __restrict__ B0, float* __restrict__ C0,
          int N0,
          const float* __restrict__ A1, const float* __restrict__ B1, float* __restrict__ C1,
          int N1,
          int K, int split) {
    extern __shared__ float smem[];
    float* As = smem;                     // [STAGES][128][SA]
    float* Bs = smem + STAGES * AW;       // [STAGES][256][SA]

    const int tid  = threadIdx.x;
    const int lane = tid & 31;
    const int wid  = tid >> 5;
    const int wm   = wid & 1;             // 2 M-warps (64 rows each)
    const int wn   = wid >> 1;            // 4 N-warps (64 cols each)
    const int t    = lane & 3;
    const int g    = lane >> 2;

    // ldmatrix per-lane address components
    const int lane15 = lane & 15;
    const int a_coff = (lane >> 4) << 2;  // 0 or 4
    const int b_row  = (lane & 7) + ((lane & 16) >> 1);
    const int b_coff = (lane & 8) >> 1;   // 0 or 4

    // job dispatch (bn fastest so A-slab sharers land in the same wave)
    const float *A, *B;
    float* C;
    int N, bm, bn;
    if (blockIdx.x < split) {
        A = A0; B = B0; C = C0; N = N0;
        int nbx = N0 >> 8;
        bm = (blockIdx.x / nbx) << 7;
        bn = (blockIdx.x % nbx) << 8;
    } else {
        A = A1; B = B1; C = C1; N = N1;
        int idx = blockIdx.x - split;
        int nbx = N1 >> 8;
        bm = (idx / nbx) << 7;
        bn = (idx % nbx) << 8;
    }

    const float* Ab = A + (size_t)bm * K;
    const float* Bb = B + (size_t)bn * K;

    // copy coordinates: A 1024 chunks (4/thread), B 2048 chunks (8/thread)
    const int rowA = tid >> 1;
    const int cA0  = (tid & 1) * 4;
    const int rowB = tid;

    float acc[4][8][4];
#pragma unroll
    for (int mf = 0; mf < 4; mf++)
#pragma unroll
        for (int nf = 0; nf < 8; nf++)
#pragma unroll
            for (int i = 0; i < 4; i++) acc[mf][nf][i] = 0.f;

#define ISSUE_TILE(st, kt)                                                           \
    do {                                                                             \
        const int _ko = (kt) << 5;                                                   \
        _Pragma("unroll")                                                            \
        for (int i = 0; i < 4; i++) {                                                \
            int c = cA0 + i;                                                         \
            uint32_t da = (uint32_t)__cvta_generic_to_shared(                        \
                As + (st) * AW + rowA * SA + c * 4);                                 \
            const float* ga = Ab + (size_t)rowA * K + _ko + c * 4;                   \
            asm volatile("cp.async.cg.shared.global [%0], [%1], 16;\n"               \
                         :: "r"(da), "l"(ga));                                       \
        }                                                                            \
        _Pragma("unroll")                                                            \
        for (int c = 0; c < 8; c++) {                                                \
            uint32_t db = (uint32_t)__cvta_generic_to_shared(                        \
                Bs + (st) * BW + rowB * SA + c * 4);                                 \
            const float* gb = Bb + (size_t)rowB * K + _ko + c * 4;                   \
            asm volatile("cp.async.cg.shared.global [%0], [%1], 16;\n"               \
                         :: "r"(db), "l"(gb));                                       \
        }                                                                            \
    } while (0)

    ISSUE_TILE(0, 0);
    asm volatile("cp.async.commit_group;\n");
    ISSUE_TILE(1, 1);
    asm volatile("cp.async.commit_group;\n");

    const int KT = K >> 5;
    int cur = 0;
    for (int kt = 0; kt < KT; kt++) {
        asm volatile("cp.async.wait_group 1;\n");
        __syncthreads();

        if (kt + STAGES - 1 < KT) {
            int nst = cur + STAGES - 1;
            if (nst >= STAGES) nst -= STAGES;
            ISSUE_TILE(nst, kt + STAGES - 1);
        }
        asm volatile("cp.async.commit_group;\n");

        const float* Ac = As + cur * AW;
        const float* Bc = Bs + cur * BW;
#pragma unroll
        for (int kk = 0; kk < 32; kk += 8) {
            uint32_t af[4][4], bf[8][2];
#pragma unroll
            for (int mf = 0; mf < 4; mf++) {
                const float* p = Ac + (wm * 64 + mf * 16 + lane15) * SA + kk + a_coff;
                ldsm_x4(af[mf][0], af[mf][1], af[mf][2], af[mf][3], p);
            }
#pragma unroll
            for (int nf2 = 0; nf2 < 4; nf2++) {
                const float* p = Bc + (wn * 64 + nf2 * 16 + b_row) * SA + kk + b_coff;
                uint32_t r0, r1, r2, r3;
                ldsm_x4(r0, r1, r2, r3, p);
                bf[2 * nf2][0] = r0; bf[2 * nf2][1] = r1;
                bf[2 * nf2 + 1][0] = r2; bf[2 * nf2 + 1][1] = r3;
            }
#pragma unroll
            for (int mf = 0; mf < 4; mf++)
#pragma unroll
                for (int nf = 0; nf < 8; nf++)
                    mma8(acc[mf][nf], af[mf], bf[nf]);
        }

        cur++;
        if (cur >= STAGES) cur = 0;
    }

    // epilogue
#pragma unroll
    for (int mf = 0; mf < 4; mf++) {
#pragma unroll
        for (int nf = 0; nf < 8; nf++) {
            int row = bm + wm * 64 + mf * 16 + g;
            int col = bn + wn * 64 + nf * 8 + t * 2;
            *(float2*)&C[(size_t)row * N + col] = make_float2(acc[mf][nf][0], acc[mf][nf][1]);
            *(float2*)&C[(size_t)(row + 8) * N + col] = make_float2(acc[mf][nf][2], acc[mf][nf][3]);
        }
    }
}

// One warp per (b, q, head). KW=4 lookback window, softmax over 4.
// Output pre-rounded to tf32 (feeds the Wo GEMM's A operand).
__global__ void __launch_bounds__(256)
attn_kernel(const float* __restrict__ qh, const float* __restrict__ kv,
            const int* __restrict__ seg, float* __restrict__ out) {
    const int gw   = (blockIdx.x * blockDim.x + threadIdx.x) >> 5;
    const int lane = threadIdx.x & 31;
    const int h    = gw & (NHEADS - 1);
    const int qrow = gw >> 4;                // 0 .. NB*LQ-1
    const int b    = qrow >> 12;             // / LQ

    const int s = seg[qrow];

    const float* qp = qh + (size_t)qrow * DATTN + h * HDIM + lane * 2;
    const float2 qv = *(const float2*)qp;

    float  sc[4];
    float2 vv[4];
#pragma unroll
    for (int w = 0; w < 4; w++) {
        int idx = s - w;
        if (idx >= 0) {
            const float* kp = kv + (size_t)(b * LKV + idx) * (2 * DATTN) + h * HDIM + lane * 2;
            float2 kvv = *(const float2*)kp;
            vv[w] = *(const float2*)(kp + DATTN);
            float p = qv.x * kvv.x + qv.y * kvv.y;
#pragma unroll
            for (int o = 16; o > 0; o >>= 1) p += __shfl_xor_sync(0xffffffffu, p, o);
            sc[w] = p * 0.125f;              // HDIM^-0.5
        } else {
            sc[w] = -INFINITY;
            vv[w] = make_float2(0.f, 0.f);
        }
    }

    float m = fmaxf(fmaxf(sc[0], sc[1]), fmaxf(sc[2], sc[3]));
    float e[4], den = 0.f;
#pragma unroll
    for (int w = 0; w < 4; w++) { e[w] = __expf(sc[w] - m); den += e[w]; }
    const float r = 1.f / den;

    float2 o = make_float2(0.f, 0.f);
#pragma unroll
    for (int w = 0; w < 4; w++) {
        o.x += e[w] * r * vv[w].x;
        o.y += e[w] * r * vv[w].y;
    }
    float2 ot;
    ot.x = __uint_as_float(f2tf32(o.x));
    ot.y = __uint_as_float(f2tf32(o.y));
    *(float2*)(out + (size_t)qrow * DATTN + h * HDIM + lane * 2) = ot;
}

extern "C" void kernel_launch(void* const* d_in, const int* in_sizes, int n_in,
                              void* d_out, int out_size) {
    const float* q      = (const float*)d_in[0];
    const float* kv_src = (const float*)d_in[1];
    const int*   seg    = (const int*)d_in[2];
    const float* Wq     = (const float*)d_in[3];
    const float* Wkv    = (const float*)d_in[4];
    const float* Wo     = (const float*)d_in[5];
    float* out = (float*)d_out;

    float *qh, *kvb, *attn, *qr, *kvsr, *wq, *wkv, *wo;
    cudaGetSymbolAddress((void**)&qh,   g_qh);
    cudaGetSymbolAddress((void**)&kvb,  g_kv);
    cudaGetSymbolAddress((void**)&attn, g_attn);
    cudaGetSymbolAddress((void**)&qr,   g_qr);
    cudaGetSymbolAddress((void**)&kvsr, g_kvsr);
    cudaGetSymbolAddress((void**)&wq,   g_wq);
    cudaGetSymbolAddress((void**)&wkv,  g_wkv);
    cudaGetSymbolAddress((void**)&wo,   g_wo);

    cudaFuncSetAttribute(gemm_tf32, cudaFuncAttributeMaxDynamicSharedMemorySize, SMEM_BYTES);

    const int K = 1024;

    // pre-round all GEMM operands to tf32
    {
        const int nq   = NB * LQ * 1024 / 4;
        const int nkvs = NB * LKV * 1024 / 4;
        const int nwq  = DATTN * 1024 / 4;
        const int nwkv = 2 * DATTN * 1024 / 4;
        const int nwo  = 1024 * DATTN / 4;
        round_tf32<<<(nq + 255) / 256, 256>>>((const float4*)q, (float4*)qr, nq);
        round_tf32<<<(nkvs + 255) / 256, 256>>>((const float4*)kv_src, (float4*)kvsr, nkvs);
        round_tf32<<<(nwq + 255) / 256, 256>>>((const float4*)Wq, (float4*)wq, nwq);
        round_tf32<<<(nwkv + 255) / 256, 256>>>((const float4*)Wkv, (float4*)wkv, nwkv);
        round_tf32<<<(nwo + 255) / 256, 256>>>((const float4*)Wo, (float4*)wo, nwo);
    }

    // Job0: qh = q @ Wq^T (16384x1024) -> 128*4 = 512 blocks
    // Job1: kv = kv_src @ Wkv^T (2048x2048) -> 16*8 = 128 blocks
    const int blocks0 = ((NB * LQ) >> 7) * (DATTN >> 8);
    const int blocks1 = ((NB * LKV) >> 7) * ((2 * DATTN) >> 8);
    gemm_tf32<<<blocks0 + blocks1, 256, SMEM_BYTES>>>(
        qr, wq, qh, DATTN,
        kvsr, wkv, kvb, 2 * DATTN,
        K, blocks0);

    // gathered windowed attention (rounds its own output to tf32)
    attn_kernel<<<(NB * LQ * NHEADS * 32) / 256, 256>>>(qh, kvb, seg, attn);

    // out = attn @ Wo^T (16384 x 1024)
    gemm_tf32<<<blocks0, 256, SMEM_BYTES>>>(
        attn, wo, out, DATTN,
        attn, wo, out, DATTN,   // unused second job
        K, blocks0);
}

// round 12
// speedup vs baseline: 1.0142x; 1.0142x over previous
#include <cuda_runtime.h>
#include <cstdint>
#include <cmath>

#define NB     4
#define LQ     4096
#define LKV    512
#define DATTN  1024
#define NHEADS 16
#define HDIM   64

// Scratch (device globals: allocation-free rule)
__device__ float g_qh[NB * LQ * DATTN];        // 64 MB
__device__ float g_kv[NB * LKV * 2 * DATTN];   // 16 MB
__device__ float g_attn[NB * LQ * DATTN];      // 64 MB
// tf32-pre-rounded operands
__device__ float g_qr[NB * LQ * 1024];
__device__ float g_kvsr[NB * LKV * 1024];
__device__ float g_wq[DATTN * 1024];
__device__ float g_wkv[2 * DATTN * 1024];
__device__ float g_wo[1024 * DATTN];

__device__ __forceinline__ uint32_t f2tf32(float x) {
    uint32_t y;
    asm("cvt.rna.tf32.f32 %0, %1;" : "=r"(y) : "f"(x));
    return y;
}

__device__ __forceinline__ void mma8(float* d, const uint32_t* a, const uint32_t* b) {
    asm volatile(
        "mma.sync.aligned.m16n8k8.row.col.f32.tf32.tf32.f32 "
        "{%0,%1,%2,%3}, {%4,%5,%6,%7}, {%8,%9}, {%0,%1,%2,%3};\n"
        : "+f"(d[0]), "+f"(d[1]), "+f"(d[2]), "+f"(d[3])
        : "r"(a[0]), "r"(a[1]), "r"(a[2]), "r"(a[3]), "r"(b[0]), "r"(b[1]));
}

__device__ __forceinline__ void ldsm_x4(uint32_t& r0, uint32_t& r1, uint32_t& r2,
                                        uint32_t& r3, const float* p) {
    uint32_t addr = (uint32_t)__cvta_generic_to_shared(p);
    asm volatile("ldmatrix.sync.aligned.m8n8.x4.shared.b16 {%0,%1,%2,%3}, [%4];"
                 : "=r"(r0), "=r"(r1), "=r"(r2), "=r"(r3) : "r"(addr));
}

// Elementwise round-to-tf32 (bits kept in fp32 storage)
__global__ void __launch_bounds__(256)
round_tf32(const float4* __restrict__ src, float4* __restrict__ dst, int n4) {
    int i = blockIdx.x * blockDim.x + threadIdx.x;
    if (i < n4) {
        float4 v = src[i];
        float4 o;
        o.x = __uint_as_float(f2tf32(v.x));
        o.y = __uint_as_float(f2tf32(v.y));
        o.z = __uint_as_float(f2tf32(v.z));
        o.w = __uint_as_float(f2tf32(v.w));
        dst[i] = o;
    }
}

#define SA     36                         // smem row stride (32 + 4 pad) words
#define STAGES 3
#define AW     (128 * SA)                 // A tile words per stage
#define BW     (128 * SA)                 // B tile words per stage
#define SMEM_BYTES (STAGES * (AW + BW) * 4)   // 110592

// C[M,N] = A[M,K] * B[N,K]^T. A,B already tf32-valued fp32 bits.
// Block tile 128M x 128N, 128 threads: 4 warps of 64x64 (2M x 2N).
// 3-stage cp.async pipeline + manual fragment double-buffering across k8 steps.
// Two jobs packed into one grid: blocks [0,split) = job0, rest = job1.
__global__ void __launch_bounds__(128)
gemm_tf32(const float* __restrict__ A0, const float* __restrict__ B0, float* __restrict__ C0,
          int N0,
          const float* __restrict__ A1, const float* __restrict__ B1, float* __restrict__ C1,
          int N1,
          int K, int split) {
    extern __shared__ float smem[];
    float* As = smem;                     // [STAGES][128][SA]
    float* Bs = smem + STAGES * AW;       // [STAGES][128][SA]

    const int tid  = threadIdx.x;
    const int lane = tid & 31;
    const int wid  = tid >> 5;
    const int wm   = wid & 1;             // 2 M-warps (64 rows each)
    const int wn   = wid >> 1;            // 2 N-warps (64 cols each)
    const int t    = lane & 3;
    const int g    = lane >> 2;

    // ldmatrix per-lane address components (identical to the verified R5 math)
    const int lane15 = lane & 15;
    const int a_coff = (lane >> 4) << 2;  // 0 or 4
    const int b_row  = (lane & 7) + ((lane & 16) >> 1);
    const int b_coff = (lane & 8) >> 1;   // 0 or 4

    // job dispatch (bn fastest)
    const float *A, *B;
    float* C;
    int N, bm, bn;
    if (blockIdx.x < split) {
        A = A0; B = B0; C = C0; N = N0;
        int nbx = N0 >> 7;
        bm = (blockIdx.x / nbx) << 7;
        bn = (blockIdx.x % nbx) << 7;
    } else {
        A = A1; B = B1; C = C1; N = N1;
        int idx = blockIdx.x - split;
        int nbx = N1 >> 7;
        bm = (idx / nbx) << 7;
        bn = (idx % nbx) << 7;
    }

    const float* Ab = A + (size_t)bm * K;
    const float* Bb = B + (size_t)bn * K;

    // copy coordinates: each thread owns one 32-word row of A and of B (8 x 16B)
    const int rowC = tid;                 // 0..127

    float acc[4][8][4];
#pragma unroll
    for (int mf = 0; mf < 4; mf++)
#pragma unroll
        for (int nf = 0; nf < 8; nf++)
#pragma unroll
            for (int i = 0; i < 4; i++) acc[mf][nf][i] = 0.f;

#define ISSUE_TILE(st, kt)                                                           \
    do {                                                                             \
        const int _ko = (kt) << 5;                                                   \
        _Pragma("unroll")                                                            \
        for (int c = 0; c < 8; c++) {                                                \
            uint32_t da = (uint32_t)__cvta_generic_to_shared(                        \
                As + (st) * AW + rowC * SA + c * 4);                                 \
            const float* ga = Ab + (size_t)rowC * K + _ko + c * 4;                   \
            asm volatile("cp.async.cg.shared.global [%0], [%1], 16;\n"               \
                         :: "r"(da), "l"(ga));                                       \
            uint32_t db = (uint32_t)__cvta_generic_to_shared(                        \
                Bs + (st) * BW + rowC * SA + c * 4);                                 \
            const float* gb = Bb + (size_t)rowC * K + _ko + c * 4;                   \
            asm volatile("cp.async.cg.shared.global [%0], [%1], 16;\n"               \
                         :: "r"(db), "l"(gb));                                       \
        }                                                                            \
    } while (0)

    ISSUE_TILE(0, 0);
    asm volatile("cp.async.commit_group;\n");
    ISSUE_TILE(1, 1);
    asm volatile("cp.async.commit_group;\n");

    // fragment buffers: double-buffered across k8 steps
    uint32_t af[2][4][4], bf[2][8][2];

#define LOADFRAG(buf, kk8)                                                           \
    do {                                                                             \
        const int _kk = (kk8) * 8;                                                   \
        _Pragma("unroll")                                                            \
        for (int mf = 0; mf < 4; mf++) {                                             \
            const float* p = Ac + (wm * 64 + mf * 16 + lane15) * SA + _kk + a_coff;  \
            ldsm_x4(af[buf][mf][0], af[buf][mf][1], af[buf][mf][2], af[buf][mf][3], p); \
        }                                                                            \
        _Pragma("unroll")                                                            \
        for (int nf2 = 0; nf2 < 4; nf2++) {                                          \
            const float* p = Bc + (wn * 64 + nf2 * 16 + b_row) * SA + _kk + b_coff;  \
            uint32_t r0, r1, r2, r3;                                                 \
            ldsm_x4(r0, r1, r2, r3, p);                                              \
            bf[buf][2 * nf2][0] = r0; bf[buf][2 * nf2][1] = r1;                      \
            bf[buf][2 * nf2 + 1][0] = r2; bf[buf][2 * nf2 + 1][1] = r3;              \
        }                                                                            \
    } while (0)

    const int KT = K >> 5;
    int cur = 0;
    for (int kt = 0; kt < KT; kt++) {
        asm volatile("cp.async.wait_group 1;\n");
        __syncthreads();

        if (kt + STAGES - 1 < KT) {
            int nst = cur + STAGES - 1;
            if (nst >= STAGES) nst -= STAGES;
            ISSUE_TILE(nst, kt + STAGES - 1);
        }
        asm volatile("cp.async.commit_group;\n");

        const float* Ac = As + cur * AW;
        const float* Bc = Bs + cur * BW;

        LOADFRAG(0, 0);
#pragma unroll
        for (int kk8 = 0; kk8 < 4; kk8++) {
            const int cb = kk8 & 1;
            if (kk8 < 3) {
                const int nb = cb ^ 1;
                LOADFRAG(nb, kk8 + 1);
            }
#pragma unroll
            for (int mf = 0; mf < 4; mf++)
#pragma unroll
                for (int nf = 0; nf < 8; nf++)
                    mma8(acc[mf][nf], af[cb][mf], bf[cb][nf]);
        }

        cur++;
        if (cur >= STAGES) cur = 0;
    }

    // epilogue
#pragma unroll
    for (int mf = 0; mf < 4; mf++) {
#pragma unroll
        for (int nf = 0; nf < 8; nf++) {
            int row = bm + wm * 64 + mf * 16 + g;
            int col = bn + wn * 64 + nf * 8 + t * 2;
            *(float2*)&C[(size_t)row * N + col] = make_float2(acc[mf][nf][0], acc[mf][nf][1]);
            *(float2*)&C[(size_t)(row + 8) * N + col] = make_float2(acc[mf][nf][2], acc[mf][nf][3]);
        }
    }
}

// One warp per (b, q, head). KW=4 lookback window, softmax over 4.
// Output pre-rounded to tf32 (feeds the Wo GEMM's A operand).
__global__ void __launch_bounds__(256)
attn_kernel(const float* __restrict__ qh, const float* __restrict__ kv,
            const int* __restrict__ seg, float* __restrict__ out) {
    const int gw   = (blockIdx.x * blockDim.x + threadIdx.x) >> 5;
    const int lane = threadIdx.x & 31;
    const int h    = gw & (NHEADS - 1);
    const int qrow = gw >> 4;                // 0 .. NB*LQ-1
    const int b    = qrow >> 12;             // / LQ

    const int s = seg[qrow];

    const float* qp = qh + (size_t)qrow * DATTN + h * HDIM + lane * 2;
    const float2 qv = *(const float2*)qp;

    float  sc[4];
    float2 vv[4];
#pragma unroll
    for (int w = 0; w < 4; w++) {
        int idx = s - w;
        if (idx >= 0) {
            const float* kp = kv + (size_t)(b * LKV + idx) * (2 * DATTN) + h * HDIM + lane * 2;
            float2 kvv = *(const float2*)kp;
            vv[w] = *(const float2*)(kp + DATTN);
            float p = qv.x * kvv.x + qv.y * kvv.y;
#pragma unroll
            for (int o = 16; o > 0; o >>= 1) p += __shfl_xor_sync(0xffffffffu, p, o);
            sc[w] = p * 0.125f;              // HDIM^-0.5
        } else {
            sc[w] = -INFINITY;
            vv[w] = make_float2(0.f, 0.f);
        }
    }

    float m = fmaxf(fmaxf(sc[0], sc[1]), fmaxf(sc[2], sc[3]));
    float e[4], den = 0.f;
#pragma unroll
    for (int w = 0; w < 4; w++) { e[w] = __expf(sc[w] - m); den += e[w]; }
    const float r = 1.f / den;

    float2 o = make_float2(0.f, 0.f);
#pragma unroll
    for (int w = 0; w < 4; w++) {
        o.x += e[w] * r * vv[w].x;
        o.y += e[w] * r * vv[w].y;
    }
    float2 ot;
    ot.x = __uint_as_float(f2tf32(o.x));
    ot.y = __uint_as_float(f2tf32(o.y));
    *(float2*)(out + (size_t)qrow * DATTN + h * HDIM + lane * 2) = ot;
}

extern "C" void kernel_launch(void* const* d_in, const int* in_sizes, int n_in,
                              void* d_out, int out_size) {
    const float* q      = (const float*)d_in[0];
    const float* kv_src = (const float*)d_in[1];
    const int*   seg    = (const int*)d_in[2];
    const float* Wq     = (const float*)d_in[3];
    const float* Wkv    = (const float*)d_in[4];
    const float* Wo     = (const float*)d_in[5];
    float* out = (float*)d_out;

    float *qh, *kvb, *attn, *qr, *kvsr, *wq, *wkv, *wo;
    cudaGetSymbolAddress((void**)&qh,   g_qh);
    cudaGetSymbolAddress((void**)&kvb,  g_kv);
    cudaGetSymbolAddress((void**)&attn, g_attn);
    cudaGetSymbolAddress((void**)&qr,   g_qr);
    cudaGetSymbolAddress((void**)&kvsr, g_kvsr);
    cudaGetSymbolAddress((void**)&wq,   g_wq);
    cudaGetSymbolAddress((void**)&wkv,  g_wkv);
    cudaGetSymbolAddress((void**)&wo,   g_wo);

    cudaFuncSetAttribute(gemm_tf32, cudaFuncAttributeMaxDynamicSharedMemorySize, SMEM_BYTES);

    const int K = 1024;

    // pre-round all GEMM operands to tf32
    {
        const int nq   = NB * LQ * 1024 / 4;
        const int nkvs = NB * LKV * 1024 / 4;
        const int nwq  = DATTN * 1024 / 4;
        const int nwkv = 2 * DATTN * 1024 / 4;
        const int nwo  = 1024 * DATTN / 4;
        round_tf32<<<(nq + 255) / 256, 256>>>((const float4*)q, (float4*)qr, nq);
        round_tf32<<<(nkvs + 255) / 256, 256>>>((const float4*)kv_src, (float4*)kvsr, nkvs);
        round_tf32<<<(nwq + 255) / 256, 256>>>((const float4*)Wq, (float4*)wq, nwq);
        round_tf32<<<(nwkv + 255) / 256, 256>>>((const float4*)Wkv, (float4*)wkv, nwkv);
        round_tf32<<<(nwo + 255) / 256, 256>>>((const float4*)Wo, (float4*)wo, nwo);
    }

    // Job0: qh = q @ Wq^T (16384x1024) -> 128*8 = 1024 blocks
    // Job1: kv = kv_src @ Wkv^T (2048x2048) -> 16*16 = 256 blocks
    const int blocks0 = ((NB * LQ) >> 7) * (DATTN >> 7);
    const int blocks1 = ((NB * LKV) >> 7) * ((2 * DATTN) >> 7);
    gemm_tf32<<<blocks0 + blocks1, 128, SMEM_BYTES>>>(
        qr, wq, qh, DATTN,
        kvsr, wkv, kvb, 2 * DATTN,
        K, blocks0);

    // gathered windowed attention (rounds its own output to tf32)
    attn_kernel<<<(NB * LQ * NHEADS * 32) / 256, 256>>>(qh, kvb, seg, attn);

    // out = attn @ Wo^T (16384 x 1024)
    gemm_tf32<<<blocks0, 128, SMEM_BYTES>>>(
        attn, wo, out, DATTN,
        attn, wo, out, DATTN,   // unused second job
        K, blocks0);
}

// round 14
// speedup vs baseline: 1.3630x; 1.3440x over previous
#include <cuda_runtime.h>
#include <cstdint>
#include <cmath>

#define NB     4
#define LQ     4096
#define LKV    512
#define DATTN  1024
#define NHEADS 16
#define HDIM   64

// Scratch (device globals: allocation-free rule)
__device__ float g_qh[NB * LQ * DATTN];        // 64 MB
__device__ float g_kv[NB * LKV * 2 * DATTN];   // 16 MB
__device__ float g_attn[NB * LQ * DATTN];      // 64 MB
// tf32-pre-rounded operands
__device__ float g_qr[NB * LQ * 1024];
__device__ float g_kvsr[NB * LKV * 1024];
__device__ float g_wq[DATTN * 1024];
__device__ float g_wkv[2 * DATTN * 1024];
__device__ float g_wo[1024 * DATTN];

__device__ __forceinline__ uint32_t f2tf32(float x) {
    uint32_t y;
    asm("cvt.rna.tf32.f32 %0, %1;" : "=r"(y) : "f"(x));
    return y;
}

__device__ __forceinline__ void mma8(float* d, const uint32_t* a, const uint32_t* b) {
    asm volatile(
        "mma.sync.aligned.m16n8k8.row.col.f32.tf32.tf32.f32 "
        "{%0,%1,%2,%3}, {%4,%5,%6,%7}, {%8,%9}, {%0,%1,%2,%3};\n"
        : "+f"(d[0]), "+f"(d[1]), "+f"(d[2]), "+f"(d[3])
        : "r"(a[0]), "r"(a[1]), "r"(a[2]), "r"(a[3]), "r"(b[0]), "r"(b[1]));
}

__device__ __forceinline__ void ldsm_x4(uint32_t& r0, uint32_t& r1, uint32_t& r2,
                                        uint32_t& r3, const float* p) {
    uint32_t addr = (uint32_t)__cvta_generic_to_shared(p);
    asm volatile("ldmatrix.sync.aligned.m8n8.x4.shared.b16 {%0,%1,%2,%3}, [%4];"
                 : "=r"(r0), "=r"(r1), "=r"(r2), "=r"(r3) : "r"(addr));
}

// Elementwise round-to-tf32 (bits kept in fp32 storage)
__global__ void __launch_bounds__(256)
round_tf32(const float4* __restrict__ src, float4* __restrict__ dst, int n4) {
    int i = blockIdx.x * blockDim.x + threadIdx.x;
    if (i < n4) {
        float4 v = src[i];
        float4 o;
        o.x = __uint_as_float(f2tf32(v.x));
        o.y = __uint_as_float(f2tf32(v.y));
        o.z = __uint_as_float(f2tf32(v.z));
        o.w = __uint_as_float(f2tf32(v.w));
        dst[i] = o;
    }
}

#define SA     36                 // smem row stride in words (32 + 4 pad)
#define STAGES 3
#define TILE_WORDS (128 * SA)     // per matrix per stage
#define SMEM_BYTES (STAGES * 2 * TILE_WORDS * 4)   // 110592

// C[M,N] = A[M,K] * B[N,K]^T. A,B already tf32-valued fp32 bits.
// Block tile 128x128x32, 256 thr = 8 warps of 32x64, 3-stage cp.async,
// prefetch interleaved into the MMA stream. 2 CTAs/SM.
// Two jobs packed into one grid: blocks [0,split) = job0, rest = job1.
__global__ void __launch_bounds__(256, 2)
gemm_tf32(const float* __restrict__ A0, const float* __restrict__ B0, float* __restrict__ C0,
          int N0,
          const float* __restrict__ A1, const float* __restrict__ B1, float* __restrict__ C1,
          int N1,
          int K, int split) {
    extern __shared__ float smem[];
    float* As = smem;                          // [STAGES][128][SA]
    float* Bs = smem + STAGES * TILE_WORDS;    // [STAGES][128][SA]

    const int tid  = threadIdx.x;
    const int lane = tid & 31;
    const int wid  = tid >> 5;
    const int wm   = wid & 3;                  // M warp: 4 x 32
    const int wn   = wid >> 2;                 // N warp: 2 x 64
    const int t    = lane & 3;
    const int g    = lane >> 2;

    // ldmatrix per-lane address components
    const int lane15 = lane & 15;
    const int a_coff = (lane >> 4) << 2;       // 0 or 4
    const int b_row  = (lane & 7) + ((lane & 16) >> 1);
    const int b_coff = (lane & 8) >> 1;        // 0 or 4

    // job dispatch (bn fastest)
    const float *A, *B;
    float* C;
    int N, bm, bn;
    if (blockIdx.x < split) {
        A = A0; B = B0; C = C0; N = N0;
        int nbx = N0 >> 7;
        bm = (blockIdx.x / nbx) << 7;
        bn = (blockIdx.x % nbx) << 7;
    } else {
        A = A1; B = B1; C = C1; N = N1;
        int idx = blockIdx.x - split;
        int nbx = N1 >> 7;
        bm = (idx / nbx) << 7;
        bn = (idx % nbx) << 7;
    }

    const float* Ab = A + (size_t)bm * K;
    const float* Bb = B + (size_t)bn * K;

    // copy coordinates: 2 threads per row, 4 x 16B chunks each, per matrix
    const int rowC = tid >> 1;                 // 0..127
    const int cc0  = (tid & 1) * 4;            // chunk base (words/4)

    float acc[2][8][4];
#pragma unroll
    for (int mf = 0; mf < 2; mf++)
#pragma unroll
        for (int nf = 0; nf < 8; nf++)
#pragma unroll
            for (int i = 0; i < 4; i++) acc[mf][nf][i] = 0.f;

#define ISSUE_A(st, kt)                                                              \
    do {                                                                             \
        const int _ko = (kt) << 5;                                                   \
        _Pragma("unroll")                                                            \
        for (int i = 0; i < 4; i++) {                                                \
            int c = cc0 + i;                                                         \
            uint32_t da = (uint32_t)__cvta_generic_to_shared(                        \
                As + (st) * TILE_WORDS + rowC * SA + c * 4);                         \
            const float* ga = Ab + (size_t)rowC * K + _ko + c * 4;                   \
            asm volatile("cp.async.cg.shared.global [%0], [%1], 16;\n"               \
                         :: "r"(da), "l"(ga));                                       \
        }                                                                            \
    } while (0)

#define ISSUE_B(st, kt)                                                              \
    do {                                                                             \
        const int _ko = (kt) << 5;                                                   \
        _Pragma("unroll")                                                            \
        for (int i = 0; i < 4; i++) {                                                \
            int c = cc0 + i;                                                         \
            uint32_t db = (uint32_t)__cvta_generic_to_shared(                        \
                Bs + (st) * TILE_WORDS + rowC * SA + c * 4);                         \
            const float* gb = Bb + (size_t)rowC * K + _ko + c * 4;                   \
            asm volatile("cp.async.cg.shared.global [%0], [%1], 16;\n"               \
                         :: "r"(db), "l"(gb));                                       \
        }                                                                            \
    } while (0)

    ISSUE_A(0, 0); ISSUE_B(0, 0);
    asm volatile("cp.async.commit_group;\n");
    ISSUE_A(1, 1); ISSUE_B(1, 1);
    asm volatile("cp.async.commit_group;\n");

    const int KT = K >> 5;
    int cur = 0;
    for (int kt = 0; kt < KT; kt++) {
        asm volatile("cp.async.wait_group 1;\n");
        __syncthreads();

        const bool pf = (kt + STAGES - 1 < KT);
        int nst = cur + STAGES - 1;
        if (nst >= STAGES) nst -= STAGES;

        const float* Ac = As + cur * TILE_WORDS;
        const float* Bc = Bs + cur * TILE_WORDS;

#pragma unroll
        for (int kk8 = 0; kk8 < 4; kk8++) {
            const int kk = kk8 * 8;
            uint32_t af[2][4], bf[8][2];
#pragma unroll
            for (int mf = 0; mf < 2; mf++) {
                const float* p = Ac + (wm * 32 + mf * 16 + lane15) * SA + kk + a_coff;
                ldsm_x4(af[mf][0], af[mf][1], af[mf][2], af[mf][3], p);
            }
#pragma unroll
            for (int nf2 = 0; nf2 < 4; nf2++) {
                const float* p = Bc + (wn * 64 + nf2 * 16 + b_row) * SA + kk + b_coff;
                uint32_t r0, r1, r2, r3;
                ldsm_x4(r0, r1, r2, r3, p);
                bf[2 * nf2][0] = r0; bf[2 * nf2][1] = r1;
                bf[2 * nf2 + 1][0] = r2; bf[2 * nf2 + 1][1] = r3;
            }
#pragma unroll
            for (int mf = 0; mf < 2; mf++)
#pragma unroll
                for (int nf = 0; nf < 8; nf++)
                    mma8(acc[mf][nf], af[mf], bf[nf]);

            // interleave next-tile global prefetch into the MMA stream
            if (kk8 == 0) {
                if (pf) ISSUE_A(nst, kt + STAGES - 1);
            } else if (kk8 == 1) {
                if (pf) ISSUE_B(nst, kt + STAGES - 1);
                asm volatile("cp.async.commit_group;\n");
            }
        }

        cur++;
        if (cur >= STAGES) cur = 0;
    }

    // epilogue
#pragma unroll
    for (int mf = 0; mf < 2; mf++) {
#pragma unroll
        for (int nf = 0; nf < 8; nf++) {
            int row = bm + wm * 32 + mf * 16 + g;
            int col = bn + wn * 64 + nf * 8 + t * 2;
            *(float2*)&C[(size_t)row * N + col] = make_float2(acc[mf][nf][0], acc[mf][nf][1]);
            *(float2*)&C[(size_t)(row + 8) * N + col] = make_float2(acc[mf][nf][2], acc[mf][nf][3]);
        }
    }
}

// One warp per (b, q, head). KW=4 lookback window, softmax over 4.
// Output pre-rounded to tf32 (feeds the Wo GEMM's A operand).
__global__ void __launch_bounds__(256)
attn_kernel(const float* __restrict__ qh, const float* __restrict__ kv,
            const int* __restrict__ seg, float* __restrict__ out) {
    const int gw   = (blockIdx.x * blockDim.x + threadIdx.x) >> 5;
    const int lane = threadIdx.x & 31;
    const int h    = gw & (NHEADS - 1);
    const int qrow = gw >> 4;                // 0 .. NB*LQ-1
    const int b    = qrow >> 12;             // / LQ

    const int s = seg[qrow];

    const float* qp = qh + (size_t)qrow * DATTN + h * HDIM + lane * 2;
    const float2 qv = *(const float2*)qp;

    float  sc[4];
    float2 vv[4];
#pragma unroll
    for (int w = 0; w < 4; w++) {
        int idx = s - w;
        if (idx >= 0) {
            const float* kp = kv + (size_t)(b * LKV + idx) * (2 * DATTN) + h * HDIM + lane * 2;
            float2 kvv = *(const float2*)kp;
            vv[w] = *(const float2*)(kp + DATTN);
            float p = qv.x * kvv.x + qv.y * kvv.y;
#pragma unroll
            for (int o = 16; o > 0; o >>= 1) p += __shfl_xor_sync(0xffffffffu, p, o);
            sc[w] = p * 0.125f;              // HDIM^-0.5
        } else {
            sc[w] = -INFINITY;
            vv[w] = make_float2(0.f, 0.f);
        }
    }

    float m = fmaxf(fmaxf(sc[0], sc[1]), fmaxf(sc[2], sc[3]));
    float e[4], den = 0.f;
#pragma unroll
    for (int w = 0; w < 4; w++) { e[w] = __expf(sc[w] - m); den += e[w]; }
    const float r = 1.f / den;

    float2 o = make_float2(0.f, 0.f);
#pragma unroll
    for (int w = 0; w < 4; w++) {
        o.x += e[w] * r * vv[w].x;
        o.y += e[w] * r * vv[w].y;
    }
    float2 ot;
    ot.x = __uint_as_float(f2tf32(o.x));
    ot.y = __uint_as_float(f2tf32(o.y));
    *(float2*)(out + (size_t)qrow * DATTN + h * HDIM + lane * 2) = ot;
}

extern "C" void kernel_launch(void* const* d_in, const int* in_sizes, int n_in,
                              void* d_out, int out_size) {
    const float* q      = (const float*)d_in[0];
    const float* kv_src = (const float*)d_in[1];
    const int*   seg    = (const int*)d_in[2];
    const float* Wq     = (const float*)d_in[3];
    const float* Wkv    = (const float*)d_in[4];
    const float* Wo     = (const float*)d_in[5];
    float* out = (float*)d_out;

    float *qh, *kvb, *attn, *qr, *kvsr, *wq, *wkv, *wo;
    cudaGetSymbolAddress((void**)&qh,   g_qh);
    cudaGetSymbolAddress((void**)&kvb,  g_kv);
    cudaGetSymbolAddress((void**)&attn, g_attn);
    cudaGetSymbolAddress((void**)&qr,   g_qr);
    cudaGetSymbolAddress((void**)&kvsr, g_kvsr);
    cudaGetSymbolAddress((void**)&wq,   g_wq);
    cudaGetSymbolAddress((void**)&wkv,  g_wkv);
    cudaGetSymbolAddress((void**)&wo,   g_wo);

    cudaFuncSetAttribute(gemm_tf32, cudaFuncAttributeMaxDynamicSharedMemorySize, SMEM_BYTES);

    const int K = 1024;

    // pre-round all GEMM operands to tf32
    {
        const int nq   = NB * LQ * 1024 / 4;
        const int nkvs = NB * LKV * 1024 / 4;
        const int nwq  = DATTN * 1024 / 4;
        const int nwkv = 2 * DATTN * 1024 / 4;
        const int nwo  = 1024 * DATTN / 4;
        round_tf32<<<(nq + 255) / 256, 256>>>((const float4*)q, (float4*)qr, nq);
        round_tf32<<<(nkvs + 255) / 256, 256>>>((const float4*)kv_src, (float4*)kvsr, nkvs);
        round_tf32<<<(nwq + 255) / 256, 256>>>((const float4*)Wq, (float4*)wq, nwq);
        round_tf32<<<(nwkv + 255) / 256, 256>>>((const float4*)Wkv, (float4*)wkv, nwkv);
        round_tf32<<<(nwo + 255) / 256, 256>>>((const float4*)Wo, (float4*)wo, nwo);
    }

    // Job0: qh = q @ Wq^T (16384x1024) -> 1024 blocks
    // Job1: kv = kv_src @ Wkv^T (2048x2048) -> 256 blocks
    const int blocks0 = ((NB * LQ) >> 7) * (DATTN >> 7);
    const int blocks1 = ((NB * LKV) >> 7) * ((2 * DATTN) >> 7);
    gemm_tf32<<<blocks0 + blocks1, 256, SMEM_BYTES>>>(
        qr, wq, qh, DATTN,
        kvsr, wkv, kvb, 2 * DATTN,
        K, blocks0);

    // gathered windowed attention (rounds its own output to tf32)
    attn_kernel<<<(NB * LQ * NHEADS * 32) / 256, 256>>>(qh, kvb, seg, attn);

    // out = attn @ Wo^T (16384 x 1024)
    gemm_tf32<<<blocks0, 256, SMEM_BYTES>>>(
        attn, wo, out, DATTN,
        attn, wo, out, DATTN,   // unused second job
        K, blocks0);
}

// round 15
// speedup vs baseline: 1.6571x; 1.2158x over previous
#include <cuda_runtime.h>
#include <cstdint>
#include <cmath>

#define NB     4
#define LQ     4096
#define LKV    512
#define DATTN  1024
#define NHEADS 16
#define HDIM   64

// Scratch (device globals: allocation-free rule)
__device__ float g_qh[NB * LQ * DATTN];        // 64 MB
__device__ float g_kv[NB * LKV * 2 * DATTN];   // 16 MB
__device__ float g_attn[NB * LQ * DATTN];      // 64 MB
// tf32-pre-rounded operands
__device__ float g_qr[NB * LQ * 1024];
__device__ float g_kvsr[NB * LKV * 1024];
__device__ float g_wq[DATTN * 1024];
__device__ float g_wkv[2 * DATTN * 1024];
__device__ float g_wo[1024 * DATTN];

__device__ __forceinline__ uint32_t f2tf32(float x) {
    uint32_t y;
    asm("cvt.rna.tf32.f32 %0, %1;" : "=r"(y) : "f"(x));
    return y;
}

__device__ __forceinline__ void mma8(float* d, const uint32_t* a, const uint32_t* b) {
    asm volatile(
        "mma.sync.aligned.m16n8k8.row.col.f32.tf32.tf32.f32 "
        "{%0,%1,%2,%3}, {%4,%5,%6,%7}, {%8,%9}, {%0,%1,%2,%3};\n"
        : "+f"(d[0]), "+f"(d[1]), "+f"(d[2]), "+f"(d[3])
        : "r"(a[0]), "r"(a[1]), "r"(a[2]), "r"(a[3]), "r"(b[0]), "r"(b[1]));
}

__device__ __forceinline__ void ldsm_x4(uint32_t& r0, uint32_t& r1, uint32_t& r2,
                                        uint32_t& r3, const float* p) {
    uint32_t addr = (uint32_t)__cvta_generic_to_shared(p);
    asm volatile("ldmatrix.sync.aligned.m8n8.x4.shared.b16 {%0,%1,%2,%3}, [%4];"
                 : "=r"(r0), "=r"(r1), "=r"(r2), "=r"(r3) : "r"(addr));
}

// Batched elementwise round-to-tf32: 5 (src,dst) pairs in one launch.
__global__ void __launch_bounds__(256)
round_all(const float4* __restrict__ s0, float4* __restrict__ d0, int n0,
          const float4* __restrict__ s1, float4* __restrict__ d1, int n1,
          const float4* __restrict__ s2, float4* __restrict__ d2, int n2,
          const float4* __restrict__ s3, float4* __restrict__ d3, int n3,
          const float4* __restrict__ s4, float4* __restrict__ d4, int n4) {
    int i = blockIdx.x * blockDim.x + threadIdx.x;
    const float4* s;
    float4* d;
    if (i < n0) { s = s0; d = d0; }
    else {
        i -= n0;
        if (i < n1) { s = s1; d = d1; }
        else {
            i -= n1;
            if (i < n2) { s = s2; d = d2; }
            else {
                i -= n2;
                if (i < n3) { s = s3; d = d3; }
                else {
                    i -= n3;
                    if (i >= n4) return;
                    s = s4; d = d4;
                }
            }
        }
    }
    float4 v = s[i];
    float4 o;
    o.x = __uint_as_float(f2tf32(v.x));
    o.y = __uint_as_float(f2tf32(v.y));
    o.z = __uint_as_float(f2tf32(v.z));
    o.w = __uint_as_float(f2tf32(v.w));
    d[i] = o;
}

#define SA     36                 // smem row stride in words (32 + 4 pad)
#define STAGES 3
#define TILE_WORDS (128 * SA)     // per matrix per stage
#define SMEM_BYTES (STAGES * 2 * TILE_WORDS * 4)   // 110592

// C[M,N] = A[M,K] * B[N,K]^T. A,B already tf32-valued fp32 bits.
// Block tile 128x128x32, 256 thr = 8 warps of 32x64, 3-stage cp.async, 2 CTAs/SM.
// (Exact R5-passing structure.) Two jobs packed into one grid.
__global__ void __launch_bounds__(256, 2)
gemm_tf32(const float* __restrict__ A0, const float* __restrict__ B0, float* __restrict__ C0,
          int N0,
          const float* __restrict__ A1, const float* __restrict__ B1, float* __restrict__ C1,
          int N1,
          int K, int split) {
    extern __shared__ float smem[];
    float* As = smem;                          // [STAGES][128][SA]
    float* Bs = smem + STAGES * TILE_WORDS;    // [STAGES][128][SA]

    const int tid  = threadIdx.x;
    const int lane = tid & 31;
    const int wid  = tid >> 5;
    const int wm   = wid & 3;                  // M warp: 4 x 32
    const int wn   = wid >> 2;                 // N warp: 2 x 64
    const int t    = lane & 3;
    const int g    = lane >> 2;

    // ldmatrix per-lane address components
    const int lane15 = lane & 15;
    const int a_coff = (lane >> 4) << 2;       // 0 or 4
    const int b_row  = (lane & 7) + ((lane & 16) >> 1);
    const int b_coff = (lane & 8) >> 1;        // 0 or 4

    // job dispatch (bn fastest)
    const float *A, *B;
    float* C;
    int N, bm, bn;
    if (blockIdx.x < split) {
        A = A0; B = B0; C = C0; N = N0;
        int nbx = N0 >> 7;
        bm = (blockIdx.x / nbx) << 7;
        bn = (blockIdx.x % nbx) << 7;
    } else {
        A = A1; B = B1; C = C1; N = N1;
        int idx = blockIdx.x - split;
        int nbx = N1 >> 7;
        bm = (idx / nbx) << 7;
        bn = (idx % nbx) << 7;
    }

    const float* Ab = A + (size_t)bm * K;
    const float* Bb = B + (size_t)bn * K;

    float acc[2][8][4];
#pragma unroll
    for (int mf = 0; mf < 2; mf++)
#pragma unroll
        for (int nf = 0; nf < 8; nf++)
#pragma unroll
            for (int i = 0; i < 4; i++) acc[mf][nf][i] = 0.f;

#define ISSUE_TILE(st, kt)                                                           \
    do {                                                                             \
        const int _ko = (kt) << 5;                                                   \
        _Pragma("unroll")                                                            \
        for (int p = 0; p < 4; p++) {                                                \
            int c = tid + p * 256;                                                   \
            int row = c >> 3, cc = c & 7;                                            \
            uint32_t da = (uint32_t)__cvta_generic_to_shared(                        \
                As + (st) * TILE_WORDS + row * SA + cc * 4);                         \
            const float* ga = Ab + (size_t)row * K + _ko + cc * 4;                   \
            asm volatile("cp.async.cg.shared.global [%0], [%1], 16;\n"               \
                         :: "r"(da), "l"(ga));                                       \
            uint32_t db = (uint32_t)__cvta_generic_to_shared(                        \
                Bs + (st) * TILE_WORDS + row * SA + cc * 4);                         \
            const float* gb = Bb + (size_t)row * K + _ko + cc * 4;                   \
            asm volatile("cp.async.cg.shared.global [%0], [%1], 16;\n"               \
                         :: "r"(db), "l"(gb));                                       \
        }                                                                            \
    } while (0)

    ISSUE_TILE(0, 0);
    asm volatile("cp.async.commit_group;\n");
    ISSUE_TILE(1, 1);
    asm volatile("cp.async.commit_group;\n");

    const int KT = K >> 5;
    int cur = 0;
    for (int kt = 0; kt < KT; kt++) {
        asm volatile("cp.async.wait_group 1;\n");
        __syncthreads();

        if (kt + STAGES - 1 < KT) {
            int nst = cur + STAGES - 1;
            if (nst >= STAGES) nst -= STAGES;
            ISSUE_TILE(nst, kt + STAGES - 1);
        }
        asm volatile("cp.async.commit_group;\n");

        const float* Ac = As + cur * TILE_WORDS;
        const float* Bc = Bs + cur * TILE_WORDS;
#pragma unroll
        for (int kk = 0; kk < 32; kk += 8) {
            uint32_t af[2][4], bf[8][2];
#pragma unroll
            for (int mf = 0; mf < 2; mf++) {
                const float* p = Ac + (wm * 32 + mf * 16 + lane15) * SA + kk + a_coff;
                ldsm_x4(af[mf][0], af[mf][1], af[mf][2], af[mf][3], p);
            }
#pragma unroll
            for (int nf2 = 0; nf2 < 4; nf2++) {
                const float* p = Bc + (wn * 64 + nf2 * 16 + b_row) * SA + kk + b_coff;
                uint32_t r0, r1, r2, r3;
                ldsm_x4(r0, r1, r2, r3, p);
                bf[2 * nf2][0] = r0; bf[2 * nf2][1] = r1;
                bf[2 * nf2 + 1][0] = r2; bf[2 * nf2 + 1][1] = r3;
            }
#pragma unroll
            for (int mf = 0; mf < 2; mf++)
#pragma unroll
                for (int nf = 0; nf < 8; nf++)
                    mma8(acc[mf][nf], af[mf], bf[nf]);
        }

        cur++;
        if (cur >= STAGES) cur = 0;
    }

    // epilogue
#pragma unroll
    for (int mf = 0; mf < 2; mf++) {
#pragma unroll
        for (int nf = 0; nf < 8; nf++) {
            int row = bm + wm * 32 + mf * 16 + g;
            int col = bn + wn * 64 + nf * 8 + t * 2;
            *(float2*)&C[(size_t)row * N + col] = make_float2(acc[mf][nf][0], acc[mf][nf][1]);
            *(float2*)&C[(size_t)(row + 8) * N + col] = make_float2(acc[mf][nf][2], acc[mf][nf][3]);
        }
    }
}

// One warp per (b, q, head). KW=4 lookback window, softmax over 4.
// Output pre-rounded to tf32 (feeds the Wo GEMM's A operand).
__global__ void __launch_bounds__(256)
attn_kernel(const float* __restrict__ qh, const float* __restrict__ kv,
            const int* __restrict__ seg, float* __restrict__ out) {
    const int gw   = (blockIdx.x * blockDim.x + threadIdx.x) >> 5;
    const int lane = threadIdx.x & 31;
    const int h    = gw & (NHEADS - 1);
    const int qrow = gw >> 4;                // 0 .. NB*LQ-1
    const int b    = qrow >> 12;             // / LQ

    const int s = seg[qrow];

    const float* qp = qh + (size_t)qrow * DATTN + h * HDIM + lane * 2;
    const float2 qv = *(const float2*)qp;

    float  sc[4];
    float2 vv[4];
#pragma unroll
    for (int w = 0; w < 4; w++) {
        int idx = s - w;
        if (idx >= 0) {
            const float* kp = kv + (size_t)(b * LKV + idx) * (2 * DATTN) + h * HDIM + lane * 2;
            float2 kvv = *(const float2*)kp;
            vv[w] = *(const float2*)(kp + DATTN);
            float p = qv.x * kvv.x + qv.y * kvv.y;
#pragma unroll
            for (int o = 16; o > 0; o >>= 1) p += __shfl_xor_sync(0xffffffffu, p, o);
            sc[w] = p * 0.125f;              // HDIM^-0.5
        } else {
            sc[w] = -INFINITY;
            vv[w] = make_float2(0.f, 0.f);
        }
    }

    float m = fmaxf(fmaxf(sc[0], sc[1]), fmaxf(sc[2], sc[3]));
    float e[4], den = 0.f;
#pragma unroll
    for (int w = 0; w < 4; w++) { e[w] = __expf(sc[w] - m); den += e[w]; }
    const float r = 1.f / den;

    float2 o = make_float2(0.f, 0.f);
#pragma unroll
    for (int w = 0; w < 4; w++) {
        o.x += e[w] * r * vv[w].x;
        o.y += e[w] * r * vv[w].y;
    }
    float2 ot;
    ot.x = __uint_as_float(f2tf32(o.x));
    ot.y = __uint_as_float(f2tf32(o.y));
    *(float2*)(out + (size_t)qrow * DATTN + h * HDIM + lane * 2) = ot;
}

extern "C" void kernel_launch(void* const* d_in, const int* in_sizes, int n_in,
                              void* d_out, int out_size) {
    const float* q      = (const float*)d_in[0];
    const float* kv_src = (const float*)d_in[1];
    const int*   seg    = (const int*)d_in[2];
    const float* Wq     = (const float*)d_in[3];
    const float* Wkv    = (const float*)d_in[4];
    const float* Wo     = (const float*)d_in[5];
    float* out = (float*)d_out;

    float *qh, *kvb, *attn, *qr, *kvsr, *wq, *wkv, *wo;
    cudaGetSymbolAddress((void**)&qh,   g_qh);
    cudaGetSymbolAddress((void**)&kvb,  g_kv);
    cudaGetSymbolAddress((void**)&attn, g_attn);
    cudaGetSymbolAddress((void**)&qr,   g_qr);
    cudaGetSymbolAddress((void**)&kvsr, g_kvsr);
    cudaGetSymbolAddress((void**)&wq,   g_wq);
    cudaGetSymbolAddress((void**)&wkv,  g_wkv);
    cudaGetSymbolAddress((void**)&wo,   g_wo);

    cudaFuncSetAttribute(gemm_tf32, cudaFuncAttributeMaxDynamicSharedMemorySize, SMEM_BYTES);

    const int K = 1024;

    // pre-round all GEMM operands to tf32 in ONE launch
    const int nq   = NB * LQ * 1024 / 4;
    const int nkvs = NB * LKV * 1024 / 4;
    const int nwq  = DATTN * 1024 / 4;
    const int nwkv = 2 * DATTN * 1024 / 4;
    const int nwo  = 1024 * DATTN / 4;
    const int ntot = nq + nkvs + nwq + nwkv + nwo;
    round_all<<<(ntot + 255) / 256, 256>>>(
        (const float4*)q, (float4*)qr, nq,
        (const float4*)kv_src, (float4*)kvsr, nkvs,
        (const float4*)Wq, (float4*)wq, nwq,
        (const float4*)Wkv, (float4*)wkv, nwkv,
        (const float4*)Wo, (float4*)wo, nwo);

    // Job0: qh = q @ Wq^T (16384x1024) -> 1024 blocks
    // Job1: kv = kv_src @ Wkv^T (2048x2048) -> 256 blocks
    const int blocks0 = ((NB * LQ) >> 7) * (DATTN >> 7);
    const int blocks1 = ((NB * LKV) >> 7) * ((2 * DATTN) >> 7);
    gemm_tf32<<<blocks0 + blocks1, 256, SMEM_BYTES>>>(
        qr, wq, qh, DATTN,
        kvsr, wkv, kvb, 2 * DATTN,
        K, blocks0);

    // gathered windowed attention (rounds its own output to tf32)
    attn_kernel<<<(NB * LQ * NHEADS * 32) / 256, 256>>>(qh, kvb, seg, attn);

    // out = attn @ Wo^T (16384 x 1024)
    gemm_tf32<<<blocks0, 256, SMEM_BYTES>>>(
        attn, wo, out, DATTN,
        attn, wo, out, DATTN,   // unused second job
        K, blocks0);
}

// round 16
// speedup vs baseline: 2.5469x; 1.5369x over previous
#include <cuda_runtime.h>
#include <cuda_fp16.h>
#include <cstdint>
#include <cmath>

#define NB     4
#define LQ     4096
#define LKV    512
#define DATTN  1024
#define NHEADS 16
#define HDIM   64

// Scratch (device globals: allocation-free rule)
__device__ float  g_qh[NB * LQ * DATTN];         // 64 MB (fp32, attn input)
__device__ float  g_kv[NB * LKV * 2 * DATTN];    // 16 MB (fp32, attn input)
__device__ __half g_attn[NB * LQ * DATTN];       // 32 MB (fp16, G3 A operand)
// fp16-converted GEMM operands
__device__ __half g_qr[NB * LQ * 1024];
__device__ __half g_kvsr[NB * LKV * 1024];
__device__ __half g_wq[DATTN * 1024];
__device__ __half g_wkv[2 * DATTN * 1024];
__device__ __half g_wo[1024 * DATTN];

__device__ __forceinline__ void mma16(float* d, const uint32_t* a, const uint32_t* b) {
    asm volatile(
        "mma.sync.aligned.m16n8k16.row.col.f32.f16.f16.f32 "
        "{%0,%1,%2,%3}, {%4,%5,%6,%7}, {%8,%9}, {%0,%1,%2,%3};\n"
        : "+f"(d[0]), "+f"(d[1]), "+f"(d[2]), "+f"(d[3])
        : "r"(a[0]), "r"(a[1]), "r"(a[2]), "r"(a[3]), "r"(b[0]), "r"(b[1]));
}

__device__ __forceinline__ void ldsm_x4(uint32_t& r0, uint32_t& r1, uint32_t& r2,
                                        uint32_t& r3, const __half* p) {
    uint32_t addr = (uint32_t)__cvta_generic_to_shared(p);
    asm volatile("ldmatrix.sync.aligned.m8n8.x4.shared.b16 {%0,%1,%2,%3}, [%4];"
                 : "=r"(r0), "=r"(r1), "=r"(r2), "=r"(r3) : "r"(addr));
}

// Batched fp32 -> fp16 convert: 5 (src,dst) pairs in one launch.
// Each index i covers 4 floats -> 4 halves (8 bytes).
__global__ void __launch_bounds__(256)
cvt_all(const float4* __restrict__ s0, uint2* __restrict__ d0, int n0,
        const float4* __restrict__ s1, uint2* __restrict__ d1, int n1,
        const float4* __restrict__ s2, uint2* __restrict__ d2, int n2,
        const float4* __restrict__ s3, uint2* __restrict__ d3, int n3,
        const float4* __restrict__ s4, uint2* __restrict__ d4, int n4) {
    int i = blockIdx.x * blockDim.x + threadIdx.x;
    const float4* s;
    uint2* d;
    if (i < n0) { s = s0; d = d0; }
    else {
        i -= n0;
        if (i < n1) { s = s1; d = d1; }
        else {
            i -= n1;
            if (i < n2) { s = s2; d = d2; }
            else {
                i -= n2;
                if (i < n3) { s = s3; d = d3; }
                else {
                    i -= n3;
                    if (i >= n4) return;
                    s = s4; d = d4;
                }
            }
        }
    }
    float4 v = s[i];
    __half2 h01 = __floats2half2_rn(v.x, v.y);
    __half2 h23 = __floats2half2_rn(v.z, v.w);
    uint2 o;
    o.x = *reinterpret_cast<uint32_t*>(&h01);
    o.y = *reinterpret_cast<uint32_t*>(&h23);
    d[i] = o;
}

#define SH     72                  // smem row stride in halfwords (64 + 8 pad)
#define KSLAB  64                  // K elements per stage
#define STAGES 3
#define TILE_H (128 * SH)          // halfwords per matrix per stage (9216)
#define SMEM_BYTES (STAGES * 2 * TILE_H * 2)   // 110592

// C[M,N] = A[M,K] * B[N,K]^T. A,B fp16, C fp32, fp32 accumulate.
// Block tile 128x128xKSLAB, 256 thr = 8 warps of 32x64, 3-stage cp.async, 2 CTAs/SM.
// Two jobs packed into one grid: blocks [0,split) = job0, rest = job1.
__global__ void __launch_bounds__(256, 2)
gemm_fp16(const __half* __restrict__ A0, const __half* __restrict__ B0, float* __restrict__ C0,
          int N0,
          const __half* __restrict__ A1, const __half* __restrict__ B1, float* __restrict__ C1,
          int N1,
          int K, int split) {
    extern __shared__ __half smem[];
    __half* As = smem;                         // [STAGES][128][SH]
    __half* Bs = smem + STAGES * TILE_H;       // [STAGES][128][SH]

    const int tid  = threadIdx.x;
    const int lane = tid & 31;
    const int wid  = tid >> 5;
    const int wm   = wid & 3;                  // M warp: 4 x 32
    const int wn   = wid >> 2;                 // N warp: 2 x 64
    const int t    = lane & 3;
    const int g    = lane >> 2;

    // ldmatrix per-lane address components (fp16 m16n8k16 canonical)
    const int l_row = lane & 15;               // row within 16-row tile pair
    const int l_k   = (lane >> 4) * 8;         // 0 or 8 halfwords (k offset)

    // job dispatch (bn fastest)
    const __half *A, *B;
    float* C;
    int N, bm, bn;
    if (blockIdx.x < split) {
        A = A0; B = B0; C = C0; N = N0;
        int nbx = N0 >> 7;
        bm = (blockIdx.x / nbx) << 7;
        bn = (blockIdx.x % nbx) << 7;
    } else {
        A = A1; B = B1; C = C1; N = N1;
        int idx = blockIdx.x - split;
        int nbx = N1 >> 7;
        bm = (idx / nbx) << 7;
        bn = (idx % nbx) << 7;
    }

    const __half* Ab = A + (size_t)bm * K;
    const __half* Bb = B + (size_t)bn * K;

    float acc[2][8][4];
#pragma unroll
    for (int mf = 0; mf < 2; mf++)
#pragma unroll
        for (int nf = 0; nf < 8; nf++)
#pragma unroll
            for (int i = 0; i < 4; i++) acc[mf][nf][i] = 0.f;

    // copy: 128 rows x 8 chunks(16B = 8 halves) per matrix; 4 chunks/thread each
#define ISSUE_TILE(st, kt)                                                           \
    do {                                                                             \
        const int _ko = (kt) * KSLAB;                                                \
        _Pragma("unroll")                                                            \
        for (int p = 0; p < 4; p++) {                                                \
            int c = tid + p * 256;                                                   \
            int row = c >> 3, cc = c & 7;                                            \
            uint32_t da = (uint32_t)__cvta_generic_to_shared(                        \
                As + (st) * TILE_H + row * SH + cc * 8);                             \
            const __half* ga = Ab + (size_t)row * K + _ko + cc * 8;                  \
            asm volatile("cp.async.cg.shared.global [%0], [%1], 16;\n"               \
                         :: "r"(da), "l"(ga));                                       \
            uint32_t db = (uint32_t)__cvta_generic_to_shared(                        \
                Bs + (st) * TILE_H + row * SH + cc * 8);                             \
            const __half* gb = Bb + (size_t)row * K + _ko + cc * 8;                  \
            asm volatile("cp.async.cg.shared.global [%0], [%1], 16;\n"               \
                         :: "r"(db), "l"(gb));                                       \
        }                                                                            \
    } while (0)

    ISSUE_TILE(0, 0);
    asm volatile("cp.async.commit_group;\n");
    ISSUE_TILE(1, 1);
    asm volatile("cp.async.commit_group;\n");

    const int KT = K / KSLAB;
    int cur = 0;
    for (int kt = 0; kt < KT; kt++) {
        asm volatile("cp.async.wait_group 1;\n");
        __syncthreads();

        if (kt + STAGES - 1 < KT) {
            int nst = cur + STAGES - 1;
            if (nst >= STAGES) nst -= STAGES;
            ISSUE_TILE(nst, kt + STAGES - 1);
        }
        asm volatile("cp.async.commit_group;\n");

        const __half* Ac = As + cur * TILE_H;
        const __half* Bc = Bs + cur * TILE_H;
#pragma unroll
        for (int s = 0; s < 4; s++) {               // 4 k16 steps per KSLAB=64
            const int kh = s * 16;
            uint32_t af[2][4], bf[8][2];
#pragma unroll
            for (int mf = 0; mf < 2; mf++) {
                const __half* p = Ac + (wm * 32 + mf * 16 + l_row) * SH + kh + l_k;
                ldsm_x4(af[mf][0], af[mf][1], af[mf][2], af[mf][3], p);
            }
#pragma unroll
            for (int nf2 = 0; nf2 < 4; nf2++) {
                const __half* p = Bc + (wn * 64 + nf2 * 16 + l_row) * SH + kh + l_k;
                uint32_t r0, r1, r2, r3;
                ldsm_x4(r0, r1, r2, r3, p);
                bf[2 * nf2][0] = r0;     bf[2 * nf2][1] = r2;
                bf[2 * nf2 + 1][0] = r1; bf[2 * nf2 + 1][1] = r3;
            }
#pragma unroll
            for (int mf = 0; mf < 2; mf++)
#pragma unroll
                for (int nf = 0; nf < 8; nf++)
                    mma16(acc[mf][nf], af[mf], bf[nf]);
        }

        cur++;
        if (cur >= STAGES) cur = 0;
    }

    // epilogue (m16n8 C layout identical to tf32 case)
#pragma unroll
    for (int mf = 0; mf < 2; mf++) {
#pragma unroll
        for (int nf = 0; nf < 8; nf++) {
            int row = bm + wm * 32 + mf * 16 + g;
            int col = bn + wn * 64 + nf * 8 + t * 2;
            *(float2*)&C[(size_t)row * N + col] = make_float2(acc[mf][nf][0], acc[mf][nf][1]);
            *(float2*)&C[(size_t)(row + 8) * N + col] = make_float2(acc[mf][nf][2], acc[mf][nf][3]);
        }
    }
}

// One warp per (b, q, head). KW=4 lookback window, softmax over 4.
// Output converted to fp16 (feeds the Wo GEMM's A operand).
__global__ void __launch_bounds__(256)
attn_kernel(const float* __restrict__ qh, const float* __restrict__ kv,
            const int* __restrict__ seg, __half* __restrict__ out) {
    const int gw   = (blockIdx.x * blockDim.x + threadIdx.x) >> 5;
    const int lane = threadIdx.x & 31;
    const int h    = gw & (NHEADS - 1);
    const int qrow = gw >> 4;                // 0 .. NB*LQ-1
    const int b    = qrow >> 12;             // / LQ

    const int s = seg[qrow];

    const float* qp = qh + (size_t)qrow * DATTN + h * HDIM + lane * 2;
    const float2 qv = *(const float2*)qp;

    float  sc[4];
    float2 vv[4];
#pragma unroll
    for (int w = 0; w < 4; w++) {
        int idx = s - w;
        if (idx >= 0) {
            const float* kp = kv + (size_t)(b * LKV + idx) * (2 * DATTN) + h * HDIM + lane * 2;
            float2 kvv = *(const float2*)kp;
            vv[w] = *(const float2*)(kp + DATTN);
            float p = qv.x * kvv.x + qv.y * kvv.y;
#pragma unroll
            for (int o = 16; o > 0; o >>= 1) p += __shfl_xor_sync(0xffffffffu, p, o);
            sc[w] = p * 0.125f;              // HDIM^-0.5
        } else {
            sc[w] = -INFINITY;
            vv[w] = make_float2(0.f, 0.f);
        }
    }

    float m = fmaxf(fmaxf(sc[0], sc[1]), fmaxf(sc[2], sc[3]));
    float e[4], den = 0.f;
#pragma unroll
    for (int w = 0; w < 4; w++) { e[w] = __expf(sc[w] - m); den += e[w]; }
    const float r = 1.f / den;

    float2 o = make_float2(0.f, 0.f);
#pragma unroll
    for (int w = 0; w < 4; w++) {
        o.x += e[w] * r * vv[w].x;
        o.y += e[w] * r * vv[w].y;
    }
    __half2 oh = __floats2half2_rn(o.x, o.y);
    *(__half2*)(out + (size_t)qrow * DATTN + h * HDIM + lane * 2) = oh;
}

extern "C" void kernel_launch(void* const* d_in, const int* in_sizes, int n_in,
                              void* d_out, int out_size) {
    const float* q      = (const float*)d_in[0];
    const float* kv_src = (const float*)d_in[1];
    const int*   seg    = (const int*)d_in[2];
    const float* Wq     = (const float*)d_in[3];
    const float* Wkv    = (const float*)d_in[4];
    const float* Wo     = (const float*)d_in[5];
    float* out = (float*)d_out;

    float *qh, *kvb;
    __half *attn, *qr, *kvsr, *wq, *wkv, *wo;
    cudaGetSymbolAddress((void**)&qh,   g_qh);
    cudaGetSymbolAddress((void**)&kvb,  g_kv);
    cudaGetSymbolAddress((void**)&attn, g_attn);
    cudaGetSymbolAddress((void**)&qr,   g_qr);
    cudaGetSymbolAddress((void**)&kvsr, g_kvsr);
    cudaGetSymbolAddress((void**)&wq,   g_wq);
    cudaGetSymbolAddress((void**)&wkv,  g_wkv);
    cudaGetSymbolAddress((void**)&wo,   g_wo);

    cudaFuncSetAttribute(gemm_fp16, cudaFuncAttributeMaxDynamicSharedMemorySize, SMEM_BYTES);

    const int K = 1024;

    // convert all GEMM operands fp32 -> fp16 in ONE launch
    const int nq   = NB * LQ * 1024 / 4;
    const int nkvs = NB * LKV * 1024 / 4;
    const int nwq  = DATTN * 1024 / 4;
    const int nwkv = 2 * DATTN * 1024 / 4;
    const int nwo  = 1024 * DATTN / 4;
    const int ntot = nq + nkvs + nwq + nwkv + nwo;
    cvt_all<<<(ntot + 255) / 256, 256>>>(
        (const float4*)q, (uint2*)qr, nq,
        (const float4*)kv_src, (uint2*)kvsr, nkvs,
        (const float4*)Wq, (uint2*)wq, nwq,
        (const float4*)Wkv, (uint2*)wkv, nwkv,
        (const float4*)Wo, (uint2*)wo, nwo);

    // Job0: qh = q @ Wq^T (16384x1024) -> 1024 blocks
    // Job1: kv = kv_src @ Wkv^T (2048x2048) -> 256 blocks
    const int blocks0 = ((NB * LQ) >> 7) * (DATTN >> 7);
    const int blocks1 = ((NB * LKV) >> 7) * ((2 * DATTN) >> 7);
    gemm_fp16<<<blocks0 + blocks1, 256, SMEM_BYTES>>>(
        qr, wq, qh, DATTN,
        kvsr, wkv, kvb, 2 * DATTN,
        K, blocks0);

    // gathered windowed attention (fp32 in, fp16 out)
    attn_kernel<<<(NB * LQ * NHEADS * 32) / 256, 256>>>(qh, kvb, seg, attn);

    // out = attn @ Wo^T (16384 x 1024)
    gemm_fp16<<<blocks0, 256, SMEM_BYTES>>>(
        attn, wo, out, DATTN,
        attn, wo, out, DATTN,   // unused second job
        K, blocks0);
}